// round 12
// baseline (speedup 1.0000x reference)
#include <cuda_runtime.h>
#include <cuda_fp16.h>
#include <cstdint>

// Problem shape (fixed):
//   x:      [8192, 4096] f32 (A, row-major)      d_in[0]
//   weight: [4096, 4096] f32 (W, row-major)      d_in[1]
//   bias:   [4096] f32                           d_in[2]
//   sw:     [262144] f32                         d_in[3]
//   idx:    [2, 262144] i32 (rows, cols)         d_in[4]
//   out = x @ (W + scatter)^T + bias   [8192, 4096] f32
//
// R12 = R11 (fp16 m16n8k16, CTA 128x128, 4 warps of 64x64, BK=64, 3-stage
// cp.async + mbarrier pipeline, 2 CTAs/SM) with two ordering fixes:
//   1. consumer-first: full-wait + kk0 LDSMs issue BEFORE the producer's
//      empty-wait, so a lagging warp can't gate consumption of a ready tile.
//   2. early release: EMPTY(s) arrive fires right after the last LDSM batch
//      (registers hold all fragments), ~1 MMA-burst earlier than before.

#define M_DIM 8192
#define N_DIM 4096
#define K_DIM 4096

#define BM 128
#define BN 128
#define BK 64                    // halves per k-tile (128B rows)
#define STAGES 3
#define NKT (K_DIM / BK)         // 64
#define NTHREADS 128

#define A_STAGE_BYTES (BM * BK * 2)     // 16384
#define B_STAGE_BYTES (BN * BK * 2)     // 16384
#define DATA_BYTES (STAGES * (A_STAGE_BYTES + B_STAGE_BYTES))   // 98304
#define MB_OFF DATA_BYTES                 // full[s]=+s*16, empty[s]=+s*16+8
#define SMEM_TOTAL (DATA_BYTES + 64)

// Device scratch (allocation-free): fp16 copies. Touched ONLY from device code.
__device__ __half g_wt[(size_t)N_DIM * K_DIM];
__device__ __half g_x[(size_t)M_DIM * K_DIM];

// ---------------------------------------------------------------------------
// helpers
// ---------------------------------------------------------------------------
__device__ __forceinline__ uint32_t smem_u32(const void* p) {
    uint32_t a;
    asm("{ .reg .u64 t; cvta.to.shared.u64 t, %1; cvt.u32.u64 %0, t; }"
        : "=r"(a) : "l"(p));
    return a;
}

#define CP_ASYNC16(dst, src) \
    asm volatile("cp.async.cg.shared.global [%0], [%1], 16;" :: "r"(dst), "l"(src))

#define MBAR_INIT(a, n) \
    asm volatile("mbarrier.init.shared.b64 [%0], %1;" :: "r"(a), "r"((uint32_t)(n)) : "memory")
#define MBAR_ARRIVE(a) \
    asm volatile("mbarrier.arrive.shared.b64 _, [%0];" :: "r"(a) : "memory")
// arrive fires when ALL prior cp.asyncs of this thread complete
#define CP_MBAR_ARRIVE(a) \
    asm volatile("cp.async.mbarrier.arrive.noinc.shared.b64 [%0];" :: "r"(a) : "memory")

#define MBAR_WAIT(a, ph) do {                                                    \
    uint32_t _m = (a), _p = (ph), _d;                                            \
    asm volatile("{ .reg .pred p; mbarrier.try_wait.parity.acquire.cta.shared::cta.b64 p, [%1], %2;" \
                 " selp.b32 %0, 1, 0, p; }" : "=r"(_d) : "r"(_m), "r"(_p) : "memory"); \
    if (!_d) {                                                                   \
        asm volatile("{ .reg .pred P1; WL_%=: mbarrier.try_wait.parity.acquire.cta.shared::cta.b64 P1, [%0], %1, 0x989680;" \
                     " @P1 bra.uni WD_%=; bra.uni WL_%=; WD_%=: }"               \
                     :: "r"(_m), "r"(_p) : "memory");                            \
    }                                                                            \
} while (0)

#define LDSM_X4(r0, r1, r2, r3, addr)                                   \
    asm volatile("ldmatrix.sync.aligned.m8n8.x4.shared.b16 "            \
                 "{%0,%1,%2,%3}, [%4];"                                 \
                 : "=r"(r0), "=r"(r1), "=r"(r2), "=r"(r3) : "r"(addr))

__device__ __forceinline__ void mma_f16(float& c0, float& c1, float& c2, float& c3,
                                        uint32_t a0, uint32_t a1, uint32_t a2, uint32_t a3,
                                        uint32_t b0, uint32_t b1) {
    asm volatile(
        "mma.sync.aligned.m16n8k16.row.col.f32.f16.f16.f32 "
        "{%0,%1,%2,%3}, {%4,%5,%6,%7}, {%8,%9}, {%0,%1,%2,%3};"
        : "+f"(c0), "+f"(c1), "+f"(c2), "+f"(c3)
        : "r"(a0), "r"(a1), "r"(a2), "r"(a3), "r"(b0), "r"(b1));
}

// ---------------------------------------------------------------------------
// Prologue: f32 -> fp16 (RNE) converts + half scatter-add
// ---------------------------------------------------------------------------
__device__ __forceinline__ void cvt8(const float4* __restrict__ src4,
                                     uint4* __restrict__ dst, size_t i) {
    float4 a = src4[i * 2 + 0];
    float4 b = src4[i * 2 + 1];
    __half2 h0 = __floats2half2_rn(a.x, a.y);
    __half2 h1 = __floats2half2_rn(a.z, a.w);
    __half2 h2 = __floats2half2_rn(b.x, b.y);
    __half2 h3 = __floats2half2_rn(b.z, b.w);
    uint4 o;
    o.x = *reinterpret_cast<uint32_t*>(&h0);
    o.y = *reinterpret_cast<uint32_t*>(&h1);
    o.z = *reinterpret_cast<uint32_t*>(&h2);
    o.w = *reinterpret_cast<uint32_t*>(&h3);
    dst[i] = o;
}

__global__ void convert_w_kernel(const float4* __restrict__ w) {
    size_t i = (size_t)blockIdx.x * blockDim.x + threadIdx.x;
    cvt8(w, reinterpret_cast<uint4*>(g_wt), i);
}

__global__ void convert_x_kernel(const float4* __restrict__ x) {
    size_t i = (size_t)blockIdx.x * blockDim.x + threadIdx.x;
    cvt8(x, reinterpret_cast<uint4*>(g_x), i);
}

__global__ void scatter_add_kernel(const float* __restrict__ sw,
                                   const int* __restrict__ rows,
                                   const int* __restrict__ cols, int nnz) {
    int i = blockIdx.x * blockDim.x + threadIdx.x;
    if (i < nnz)
        atomicAdd(&g_wt[(size_t)rows[i] * K_DIM + cols[i]], __float2half(sw[i]));
}

// ---------------------------------------------------------------------------
// GEMM: C[M,N] = A @ W'^T + bias
// ---------------------------------------------------------------------------
__global__ __launch_bounds__(NTHREADS, 2)
void gemm_f16_kernel(const float* __restrict__ bias,
                     float* __restrict__ C) {
    extern __shared__ char smem[];
    const uint32_t sb = smem_u32(smem);

    const int tid  = threadIdx.x;
    const int wid  = tid >> 5;
    const int lane = tid & 31;
    const int lr   = lane >> 2;
    const int lq   = lane & 3;

    const int warpM = (wid >> 1) * 64;   // 0 or 64
    const int warpN = (wid & 1) * 64;    // 0 or 64

    const int bm = blockIdx.y * BM;
    const int bn = blockIdx.x * BN;

    const __half* Ab = g_x + (size_t)bm * K_DIM;
    const __half* Bb = g_wt + (size_t)bn * K_DIM;

#define FULL(s)  (sb + MB_OFF + (s) * 16)
#define EMPTY(s) (sb + MB_OFF + (s) * 16 + 8)

    if (tid == 0) {
#pragma unroll
        for (int q = 0; q < STAGES; q++) {
            MBAR_INIT(FULL(q), NTHREADS);
            MBAR_INIT(EMPTY(q), NTHREADS);
        }
    }
    __syncthreads();   // only block barrier in the kernel

    // ldmatrix lane->address mapping
    const int aRow  = warpM + (lane & 15);
    const int aCSel = lane >> 4;
    const int bRow  = warpN + (lane & 7) + ((lane >> 4) << 3);
    const int bCSel = (lane >> 3) & 1;

#define LOAD_TILE(t, s)                                                         \
    {                                                                           \
        const uint32_t ab = sb + (s) * A_STAGE_BYTES;                           \
        _Pragma("unroll")                                                       \
        for (int j = 0; j < 8; j++) {                                           \
            int i = tid + j * NTHREADS;          /* 0..1023 */                  \
            int r = i >> 3, c = i & 7;                                          \
            uint32_t dst = ab + (uint32_t)(r * 128 + ((c ^ (r & 7)) << 4));     \
            CP_ASYNC16(dst, Ab + (size_t)r * K_DIM + (t) * BK + c * 8);         \
        }                                                                       \
        const uint32_t bb = sb + STAGES * A_STAGE_BYTES + (s) * B_STAGE_BYTES;  \
        _Pragma("unroll")                                                       \
        for (int j = 0; j < 8; j++) {                                           \
            int i = tid + j * NTHREADS;          /* 0..1023 */                  \
            int r = i >> 3, c = i & 7;                                          \
            uint32_t dst = bb + (uint32_t)(r * 128 + ((c ^ (r & 7)) << 4));     \
            CP_ASYNC16(dst, Bb + (size_t)r * K_DIM + (t) * BK + c * 8);         \
        }                                                                       \
    }

    // fragment loads for one kk-step
#define LDS_FRAGS(kk, ua, ub, abase, bbase)                                     \
    {                                                                           \
        _Pragma("unroll")                                                       \
        for (int mt = 0; mt < 4; mt++) {                                        \
            const int r = aRow + mt * 16;                                       \
            const int c = 2 * (kk) + aCSel;                                     \
            const uint32_t addr =                                               \
                (abase) + (uint32_t)(r * 128 + ((c ^ (r & 7)) << 4));           \
            LDSM_X4((ua)[mt][0], (ua)[mt][1], (ua)[mt][2], (ua)[mt][3], addr);  \
        }                                                                       \
        _Pragma("unroll")                                                       \
        for (int ntp = 0; ntp < 4; ntp++) {                                     \
            const int n = bRow + ntp * 16;                                      \
            const int c = 2 * (kk) + bCSel;                                     \
            const uint32_t addr =                                               \
                (bbase) + (uint32_t)(n * 128 + ((c ^ (n & 7)) << 4));           \
            LDSM_X4((ub)[ntp][0], (ub)[ntp][1], (ub)[ntp][2], (ub)[ntp][3], addr); \
        }                                                                       \
    }

#define MMA_BURST(ua, ub)                                                       \
    {                                                                           \
        _Pragma("unroll")                                                       \
        for (int mt = 0; mt < 4; mt++)                                          \
            _Pragma("unroll")                                                   \
            for (int nt = 0; nt < 8; nt++) {                                    \
                const uint32_t b0 = (nt & 1) ? (ub)[nt >> 1][2] : (ub)[nt >> 1][0]; \
                const uint32_t b1 = (nt & 1) ? (ub)[nt >> 1][3] : (ub)[nt >> 1][1]; \
                mma_f16(acc[mt][nt][0], acc[mt][nt][1],                         \
                        acc[mt][nt][2], acc[mt][nt][3],                         \
                        (ua)[mt][0], (ua)[mt][1], (ua)[mt][2], (ua)[mt][3],     \
                        b0, b1);                                                \
            }                                                                   \
    }

    // prologue: tiles 0,1 into stages 0,1
    LOAD_TILE(0, 0);
    CP_MBAR_ARRIVE(FULL(0));
    LOAD_TILE(1, 1);
    CP_MBAR_ARRIVE(FULL(1));

    float acc[4][8][4];
#pragma unroll
    for (int i = 0; i < 4; i++)
#pragma unroll
        for (int j = 0; j < 8; j++)
#pragma unroll
            for (int q = 0; q < 4; q++) acc[i][j][q] = 0.0f;

    uint32_t fph = 0, eph = 0;
    int s = 0;                   // stage of tile t
    int sp = 2;                  // stage for prefetch (t+2)
    for (int t = 0; t < NKT; t++) {
        // consumer FIRST: tile t ready?
        MBAR_WAIT(FULL(s), (fph >> s) & 1);
        fph ^= (1u << s);

        const uint32_t abase = sb + s * A_STAGE_BYTES;
        const uint32_t bbase = sb + STAGES * A_STAGE_BYTES + s * B_STAGE_BYTES;

        uint32_t ua[4][4], ub[4][4];
        // kk=0 fragments in flight before the producer's (possibly stalling)
        // empty-wait
        LDS_FRAGS(0, ua, ub, abase, bbase);

        // producer: refill stage sp with tile t+2
        if (t + 2 < NKT) {
            if (t >= 1) {
                MBAR_WAIT(EMPTY(sp), (eph >> sp) & 1);
                eph ^= (1u << sp);
            }
            LOAD_TILE(t + 2, sp);
            CP_MBAR_ARRIVE(FULL(sp));
        }

        MMA_BURST(ua, ub);                       // kk=0
#pragma unroll
        for (int kk = 1; kk < 4; kk++) {
            LDS_FRAGS(kk, ua, ub, abase, bbase);
            if (kk == 3) MBAR_ARRIVE(EMPTY(s));  // stage s dead after last LDSM
            MMA_BURST(ua, ub);
        }

        s = (s == 2) ? 0 : s + 1;
        sp = (sp == 2) ? 0 : sp + 1;
    }

    // Epilogue: bias + store
#pragma unroll
    for (int nt = 0; nt < 8; nt++) {
        const int col = bn + warpN + nt * 8 + lq * 2;
        const float bv0 = bias[col];
        const float bv1 = bias[col + 1];
#pragma unroll
        for (int mt = 0; mt < 4; mt++) {
            const int r0 = bm + warpM + mt * 16 + lr;
            float2 v0, v1;
            v0.x = acc[mt][nt][0] + bv0;
            v0.y = acc[mt][nt][1] + bv1;
            v1.x = acc[mt][nt][2] + bv0;
            v1.y = acc[mt][nt][3] + bv1;
            *reinterpret_cast<float2*>(&C[(size_t)r0 * N_DIM + col]) = v0;
            *reinterpret_cast<float2*>(&C[(size_t)(r0 + 8) * N_DIM + col]) = v1;
        }
    }
}

// ---------------------------------------------------------------------------
// Launch
// ---------------------------------------------------------------------------
extern "C" void kernel_launch(void* const* d_in, const int* in_sizes, int n_in,
                              void* d_out, int out_size) {
    const float* x    = (const float*)d_in[0];
    const float* w    = (const float*)d_in[1];
    const float* bias = (const float*)d_in[2];
    const float* sw   = (const float*)d_in[3];
    const int*   idx  = (const int*)d_in[4];
    float*       out  = (float*)d_out;
    const int nnz = in_sizes[3];

    convert_w_kernel<<<(N_DIM * K_DIM / 8) / 256, 256>>>(
        reinterpret_cast<const float4*>(w));
    scatter_add_kernel<<<(nnz + 255) / 256, 256>>>(sw, idx, idx + nnz, nnz);
    convert_x_kernel<<<(int)(((size_t)M_DIM * K_DIM / 8) / 256), 256>>>(
        reinterpret_cast<const float4*>(x));

    cudaFuncSetAttribute(gemm_f16_kernel,
                         cudaFuncAttributeMaxDynamicSharedMemorySize, SMEM_TOTAL);
    dim3 grid(N_DIM / BN, M_DIM / BM);   // (32, 64)
    gemm_f16_kernel<<<grid, NTHREADS, SMEM_TOTAL>>>(bias, out);
}

// round 13
// speedup vs baseline: 1.0205x; 1.0205x over previous
#include <cuda_runtime.h>
#include <cuda_fp16.h>
#include <cstdint>

// Problem shape (fixed):
//   x:      [8192, 4096] f32 (A, row-major)      d_in[0]
//   weight: [4096, 4096] f32 (W, row-major)      d_in[1]
//   bias:   [4096] f32                           d_in[2]
//   sw:     [262144] f32                         d_in[3]
//   idx:    [2, 262144] i32 (rows, cols)         d_in[4]
//   out = x @ (W + scatter)^T + bias   [8192, 4096] f32
//
// R13 = R11 (best: fp16 m16n8k16, CTA 128x128, 4 warps of 64x64, BK=64,
// 3-stage cp.async + mbarrier pipeline, 2 CTAs/SM) with exactly two
// register-neutral tweaks:
//   1. EMPTY(s) released right after the last LDSM batch of the tile
//      (fragments scoped inside the kk loop as in R11 — the R12 hoist that
//      pushed regs 238->254 is NOT repeated).
//   2. producer empty-wait uses .relaxed (post-wait accesses are cp.async
//      issues only; WAR ordering comes from in-order issue + mbarrier).

#define M_DIM 8192
#define N_DIM 4096
#define K_DIM 4096

#define BM 128
#define BN 128
#define BK 64                    // halves per k-tile (128B rows)
#define STAGES 3
#define NKT (K_DIM / BK)         // 64
#define NTHREADS 128

#define A_STAGE_BYTES (BM * BK * 2)     // 16384
#define B_STAGE_BYTES (BN * BK * 2)     // 16384
#define DATA_BYTES (STAGES * (A_STAGE_BYTES + B_STAGE_BYTES))   // 98304
#define MB_OFF DATA_BYTES                 // full[s]=+s*16, empty[s]=+s*16+8
#define SMEM_TOTAL (DATA_BYTES + 64)

// Device scratch (allocation-free): fp16 copies. Touched ONLY from device code.
__device__ __half g_wt[(size_t)N_DIM * K_DIM];
__device__ __half g_x[(size_t)M_DIM * K_DIM];

// ---------------------------------------------------------------------------
// helpers
// ---------------------------------------------------------------------------
__device__ __forceinline__ uint32_t smem_u32(const void* p) {
    uint32_t a;
    asm("{ .reg .u64 t; cvta.to.shared.u64 t, %1; cvt.u32.u64 %0, t; }"
        : "=r"(a) : "l"(p));
    return a;
}

#define CP_ASYNC16(dst, src) \
    asm volatile("cp.async.cg.shared.global [%0], [%1], 16;" :: "r"(dst), "l"(src))

#define MBAR_INIT(a, n) \
    asm volatile("mbarrier.init.shared.b64 [%0], %1;" :: "r"(a), "r"((uint32_t)(n)) : "memory")
#define MBAR_ARRIVE(a) \
    asm volatile("mbarrier.arrive.shared.b64 _, [%0];" :: "r"(a) : "memory")
#define CP_MBAR_ARRIVE(a) \
    asm volatile("cp.async.mbarrier.arrive.noinc.shared.b64 [%0];" :: "r"(a) : "memory")

// acquire wait (consumer: generic LDSM reads follow)
#define MBAR_WAIT(a, ph) do {                                                    \
    uint32_t _m = (a), _p = (ph), _d;                                            \
    asm volatile("{ .reg .pred p; mbarrier.try_wait.parity.acquire.cta.shared::cta.b64 p, [%1], %2;" \
                 " selp.b32 %0, 1, 0, p; }" : "=r"(_d) : "r"(_m), "r"(_p) : "memory"); \
    if (!_d) {                                                                   \
        asm volatile("{ .reg .pred P1; WL_%=: mbarrier.try_wait.parity.acquire.cta.shared::cta.b64 P1, [%0], %1, 0x989680;" \
                     " @P1 bra.uni WD_%=; bra.uni WL_%=; WD_%=: }"               \
                     :: "r"(_m), "r"(_p) : "memory");                            \
    }                                                                            \
} while (0)

// relaxed wait (producer: post-wait smem accesses are cp.async issues only)
#define MBAR_WAIT_RELAXED(a, ph) do {                                            \
    uint32_t _m = (a), _p = (ph), _d;                                            \
    asm volatile("{ .reg .pred p; mbarrier.try_wait.parity.relaxed.cta.shared::cta.b64 p, [%1], %2;" \
                 " selp.b32 %0, 1, 0, p; }" : "=r"(_d) : "r"(_m), "r"(_p) : "memory"); \
    if (!_d) {                                                                   \
        asm volatile("{ .reg .pred P1; WL_%=: mbarrier.try_wait.parity.relaxed.cta.shared::cta.b64 P1, [%0], %1, 0x989680;" \
                     " @P1 bra.uni WD_%=; bra.uni WL_%=; WD_%=: }"               \
                     :: "r"(_m), "r"(_p) : "memory");                            \
    }                                                                            \
} while (0)

#define LDSM_X4(r0, r1, r2, r3, addr)                                   \
    asm volatile("ldmatrix.sync.aligned.m8n8.x4.shared.b16 "            \
                 "{%0,%1,%2,%3}, [%4];"                                 \
                 : "=r"(r0), "=r"(r1), "=r"(r2), "=r"(r3) : "r"(addr))

__device__ __forceinline__ void mma_f16(float& c0, float& c1, float& c2, float& c3,
                                        uint32_t a0, uint32_t a1, uint32_t a2, uint32_t a3,
                                        uint32_t b0, uint32_t b1) {
    asm volatile(
        "mma.sync.aligned.m16n8k16.row.col.f32.f16.f16.f32 "
        "{%0,%1,%2,%3}, {%4,%5,%6,%7}, {%8,%9}, {%0,%1,%2,%3};"
        : "+f"(c0), "+f"(c1), "+f"(c2), "+f"(c3)
        : "r"(a0), "r"(a1), "r"(a2), "r"(a3), "r"(b0), "r"(b1));
}

// ---------------------------------------------------------------------------
// Prologue: f32 -> fp16 (RNE) converts + half scatter-add
// ---------------------------------------------------------------------------
__device__ __forceinline__ void cvt8(const float4* __restrict__ src4,
                                     uint4* __restrict__ dst, size_t i) {
    float4 a = src4[i * 2 + 0];
    float4 b = src4[i * 2 + 1];
    __half2 h0 = __floats2half2_rn(a.x, a.y);
    __half2 h1 = __floats2half2_rn(a.z, a.w);
    __half2 h2 = __floats2half2_rn(b.x, b.y);
    __half2 h3 = __floats2half2_rn(b.z, b.w);
    uint4 o;
    o.x = *reinterpret_cast<uint32_t*>(&h0);
    o.y = *reinterpret_cast<uint32_t*>(&h1);
    o.z = *reinterpret_cast<uint32_t*>(&h2);
    o.w = *reinterpret_cast<uint32_t*>(&h3);
    dst[i] = o;
}

__global__ void convert_w_kernel(const float4* __restrict__ w) {
    size_t i = (size_t)blockIdx.x * blockDim.x + threadIdx.x;
    cvt8(w, reinterpret_cast<uint4*>(g_wt), i);
}

__global__ void convert_x_kernel(const float4* __restrict__ x) {
    size_t i = (size_t)blockIdx.x * blockDim.x + threadIdx.x;
    cvt8(x, reinterpret_cast<uint4*>(g_x), i);
}

__global__ void scatter_add_kernel(const float* __restrict__ sw,
                                   const int* __restrict__ rows,
                                   const int* __restrict__ cols, int nnz) {
    int i = blockIdx.x * blockDim.x + threadIdx.x;
    if (i < nnz)
        atomicAdd(&g_wt[(size_t)rows[i] * K_DIM + cols[i]], __float2half(sw[i]));
}

// ---------------------------------------------------------------------------
// GEMM: C[M,N] = A @ W'^T + bias
// ---------------------------------------------------------------------------
__global__ __launch_bounds__(NTHREADS, 2)
void gemm_f16_kernel(const float* __restrict__ bias,
                     float* __restrict__ C) {
    extern __shared__ char smem[];
    const uint32_t sb = smem_u32(smem);

    const int tid  = threadIdx.x;
    const int wid  = tid >> 5;
    const int lane = tid & 31;
    const int lr   = lane >> 2;
    const int lq   = lane & 3;

    const int warpM = (wid >> 1) * 64;   // 0 or 64
    const int warpN = (wid & 1) * 64;    // 0 or 64

    const int bm = blockIdx.y * BM;
    const int bn = blockIdx.x * BN;

    const __half* Ab = g_x + (size_t)bm * K_DIM;
    const __half* Bb = g_wt + (size_t)bn * K_DIM;

#define FULL(s)  (sb + MB_OFF + (s) * 16)
#define EMPTY(s) (sb + MB_OFF + (s) * 16 + 8)

    if (tid == 0) {
#pragma unroll
        for (int q = 0; q < STAGES; q++) {
            MBAR_INIT(FULL(q), NTHREADS);
            MBAR_INIT(EMPTY(q), NTHREADS);
        }
    }
    __syncthreads();   // only block barrier in the kernel

    // ldmatrix lane->address mapping
    const int aRow  = warpM + (lane & 15);
    const int aCSel = lane >> 4;
    const int bRow  = warpN + (lane & 7) + ((lane >> 4) << 3);
    const int bCSel = (lane >> 3) & 1;

#define LOAD_TILE(t, s)                                                         \
    {                                                                           \
        const uint32_t ab = sb + (s) * A_STAGE_BYTES;                           \
        _Pragma("unroll")                                                       \
        for (int j = 0; j < 8; j++) {                                           \
            int i = tid + j * NTHREADS;          /* 0..1023 */                  \
            int r = i >> 3, c = i & 7;                                          \
            uint32_t dst = ab + (uint32_t)(r * 128 + ((c ^ (r & 7)) << 4));     \
            CP_ASYNC16(dst, Ab + (size_t)r * K_DIM + (t) * BK + c * 8);         \
        }                                                                       \
        const uint32_t bb = sb + STAGES * A_STAGE_BYTES + (s) * B_STAGE_BYTES;  \
        _Pragma("unroll")                                                       \
        for (int j = 0; j < 8; j++) {                                           \
            int i = tid + j * NTHREADS;          /* 0..1023 */                  \
            int r = i >> 3, c = i & 7;                                          \
            uint32_t dst = bb + (uint32_t)(r * 128 + ((c ^ (r & 7)) << 4));     \
            CP_ASYNC16(dst, Bb + (size_t)r * K_DIM + (t) * BK + c * 8);         \
        }                                                                       \
    }

    // prologue: tiles 0,1 into stages 0,1
    LOAD_TILE(0, 0);
    CP_MBAR_ARRIVE(FULL(0));
    LOAD_TILE(1, 1);
    CP_MBAR_ARRIVE(FULL(1));

    float acc[4][8][4];
#pragma unroll
    for (int i = 0; i < 4; i++)
#pragma unroll
        for (int j = 0; j < 8; j++)
#pragma unroll
            for (int q = 0; q < 4; q++) acc[i][j][q] = 0.0f;

    uint32_t fph = 0, eph = 0;
    int s = 0;                   // stage of tile t
    int sp = 2;                  // stage for prefetch (t+2)
    for (int t = 0; t < NKT; t++) {
        // producer: refill stage sp with tile t+2
        if (t + 2 < NKT) {
            if (t >= 1) {
                MBAR_WAIT_RELAXED(EMPTY(sp), (eph >> sp) & 1);
                eph ^= (1u << sp);
            }
            LOAD_TILE(t + 2, sp);
            CP_MBAR_ARRIVE(FULL(sp));
        }

        // consumer: wait for tile t
        MBAR_WAIT(FULL(s), (fph >> s) & 1);
        fph ^= (1u << s);

        const uint32_t abase = sb + s * A_STAGE_BYTES;
        const uint32_t bbase = sb + STAGES * A_STAGE_BYTES + s * B_STAGE_BYTES;

#pragma unroll
        for (int kk = 0; kk < 4; kk++) {
            uint32_t ua[4][4], ub[4][4];
#pragma unroll
            for (int mt = 0; mt < 4; mt++) {
                const int r = aRow + mt * 16;
                const int c = 2 * kk + aCSel;
                const uint32_t addr =
                    abase + (uint32_t)(r * 128 + ((c ^ (r & 7)) << 4));
                LDSM_X4(ua[mt][0], ua[mt][1], ua[mt][2], ua[mt][3], addr);
            }
#pragma unroll
            for (int ntp = 0; ntp < 4; ntp++) {
                const int n = bRow + ntp * 16;
                const int c = 2 * kk + bCSel;
                const uint32_t addr =
                    bbase + (uint32_t)(n * 128 + ((c ^ (n & 7)) << 4));
                LDSM_X4(ub[ntp][0], ub[ntp][1], ub[ntp][2], ub[ntp][3], addr);
            }
            // after the LAST LDSM batch of this tile, stage s is dead:
            // release it before the final MMA burst (register-neutral)
            if (kk == 3) MBAR_ARRIVE(EMPTY(s));
#pragma unroll
            for (int mt = 0; mt < 4; mt++)
#pragma unroll
                for (int nt = 0; nt < 8; nt++) {
                    const uint32_t b0 = (nt & 1) ? ub[nt >> 1][2] : ub[nt >> 1][0];
                    const uint32_t b1 = (nt & 1) ? ub[nt >> 1][3] : ub[nt >> 1][1];
                    mma_f16(acc[mt][nt][0], acc[mt][nt][1],
                            acc[mt][nt][2], acc[mt][nt][3],
                            ua[mt][0], ua[mt][1], ua[mt][2], ua[mt][3],
                            b0, b1);
                }
        }

        s = (s == 2) ? 0 : s + 1;
        sp = (sp == 2) ? 0 : sp + 1;
    }

    // Epilogue: bias + store
#pragma unroll
    for (int nt = 0; nt < 8; nt++) {
        const int col = bn + warpN + nt * 8 + lq * 2;
        const float bv0 = bias[col];
        const float bv1 = bias[col + 1];
#pragma unroll
        for (int mt = 0; mt < 4; mt++) {
            const int r0 = bm + warpM + mt * 16 + lr;
            float2 v0, v1;
            v0.x = acc[mt][nt][0] + bv0;
            v0.y = acc[mt][nt][1] + bv1;
            v1.x = acc[mt][nt][2] + bv0;
            v1.y = acc[mt][nt][3] + bv1;
            *reinterpret_cast<float2*>(&C[(size_t)r0 * N_DIM + col]) = v0;
            *reinterpret_cast<float2*>(&C[(size_t)(r0 + 8) * N_DIM + col]) = v1;
        }
    }
}

// ---------------------------------------------------------------------------
// Launch
// ---------------------------------------------------------------------------
extern "C" void kernel_launch(void* const* d_in, const int* in_sizes, int n_in,
                              void* d_out, int out_size) {
    const float* x    = (const float*)d_in[0];
    const float* w    = (const float*)d_in[1];
    const float* bias = (const float*)d_in[2];
    const float* sw   = (const float*)d_in[3];
    const int*   idx  = (const int*)d_in[4];
    float*       out  = (float*)d_out;
    const int nnz = in_sizes[3];

    convert_w_kernel<<<(N_DIM * K_DIM / 8) / 256, 256>>>(
        reinterpret_cast<const float4*>(w));
    scatter_add_kernel<<<(nnz + 255) / 256, 256>>>(sw, idx, idx + nnz, nnz);
    convert_x_kernel<<<(int)(((size_t)M_DIM * K_DIM / 8) / 256), 256>>>(
        reinterpret_cast<const float4*>(x));

    cudaFuncSetAttribute(gemm_f16_kernel,
                         cudaFuncAttributeMaxDynamicSharedMemorySize, SMEM_TOTAL);
    dim3 grid(N_DIM / BN, M_DIM / BM);   // (32, 64)
    gemm_f16_kernel<<<grid, NTHREADS, SMEM_TOTAL>>>(bias, out);
}